// round 1
// baseline (speedup 1.0000x reference)
#include <cuda_runtime.h>
#include <math.h>

#define BB 4
#define NN 32
#define DD 128
#define HH 8
#define NCC 27
#define DKK 16
#define DFF 512
#define LL (NCC*NN)        // 864
#define ROWS (BB*LL)       // 3456

// ---------------- scratch (static device globals; no allocation) -------------
__device__ __align__(16) float g_base[ROWS*DD];
__device__ __align__(16) float g_tvec[ROWS*DD];
__device__ __align__(16) float g_Pk[ROWS*DD];
__device__ __align__(16) float g_Pv[ROWS*DD];
__device__ __align__(16) float g_Tk[ROWS*DD];
__device__ __align__(16) float g_Tv[ROWS*DD];
__device__ float g_mb[ROWS], g_ssb[ROWS];   // mean(base row), sum(base^2)
__device__ float g_mt[ROWS], g_sst[ROWS];   // mean(tvec row), sum(tvec^2)
__device__ float g_S[BB*NCC*NN*NN];         // base[b,c,n] . tvec[b,c,i]
__device__ __align__(16) float g_Q[BB*NN*DD];
__device__ __align__(16) float g_arow[BB*NN*DD];
__device__ __align__(16) float g_y[BB*NN*DD];
__device__ float g_uk[DD], g_uv[DD], g_ck[DD], g_cv[DD];

__inline__ __device__ float warpSum(float v){
    #pragma unroll
    for (int o = 16; o; o >>= 1) v += __shfl_down_sync(0xffffffffu, v, o);
    return v;
}

// ---------------- K1: base/tvec + per-row stats ------------------------------
__global__ void k_prep(const float* __restrict__ x, const float* __restrict__ coords,
                       const float* __restrict__ Wp, const float* __restrict__ bp)
{
    int r = blockIdx.x;                 // r = (b*NC + c)*N + n = b*864 + l
    int n = r & 31;
    int b = r / (NCC*NN);
    int d = threadIdx.x;                // 128

    float c0 = coords[r*3+0], c1 = coords[r*3+1], c2 = coords[r*3+2];
    float t  = c0*Wp[d] + c1*Wp[DD+d] + c2*Wp[2*DD+d];
    float bs = x[(b*NN+n)*DD + d] + t + bp[d];
    g_tvec[r*DD + d] = t;
    g_base[r*DD + d] = bs;

    __shared__ float sm[4][4];
    float s0 = warpSum(t), s1 = warpSum(t*t), s2 = warpSum(bs), s3 = warpSum(bs*bs);
    int lane = d & 31, w = d >> 5;
    if (lane == 0){ sm[w][0]=s0; sm[w][1]=s1; sm[w][2]=s2; sm[w][3]=s3; }
    __syncthreads();
    if (d < 4){
        float a = sm[0][d] + sm[1][d] + sm[2][d] + sm[3][d];
        if (d == 0) g_mt[r]  = a * (1.0f/128.0f);
        if (d == 1) g_sst[r] = a;
        if (d == 2) g_mb[r]  = a * (1.0f/128.0f);
        if (d == 3) g_ssb[r] = a;
    }
}

// ---------------- K2: hoisted GEMMs Pk/Pv and Tk/Tv --------------------------
// Rows 0..3455 = (base ⊙ g1) -> Pk/Pv ; rows 3456..6911 = (tvec ⊙ g1) -> Tk/Tv
__global__ void k_gemm_pt(const float* __restrict__ Wk, const float* __restrict__ Wv,
                          const float* __restrict__ g1)
{
    __shared__ __align__(16) float As[32][128];
    int m0 = blockIdx.x * 32;           // 216 blocks
    const float* src; float* outK; float* outV; int ro;
    if (m0 < ROWS){ src = g_base + m0*DD;        outK = g_Pk; outV = g_Pv; ro = m0; }
    else          { src = g_tvec + (m0-ROWS)*DD; outK = g_Tk; outV = g_Tv; ro = m0-ROWS; }

    int tid = threadIdx.x;              // 256
    for (int idx = tid; idx < 32*128; idx += 256){
        int dd = idx & 127;
        As[idx >> 7][dd] = src[idx] * g1[dd];
    }
    __syncthreads();

    int j = tid & 127;
    const float* W = (tid < 128) ? Wk : Wv;
    float*     out = (tid < 128) ? outK : outV;

    float acc[32];
    #pragma unroll
    for (int r = 0; r < 32; r++) acc[r] = 0.0f;

    for (int k4 = 0; k4 < 32; k4++){
        float w0 = W[(4*k4+0)*128 + j];
        float w1 = W[(4*k4+1)*128 + j];
        float w2 = W[(4*k4+2)*128 + j];
        float w3 = W[(4*k4+3)*128 + j];
        #pragma unroll
        for (int r = 0; r < 32; r++){
            float4 a = *(const float4*)&As[r][4*k4];
            acc[r] = fmaf(a.x, w0, fmaf(a.y, w1, fmaf(a.z, w2, fmaf(a.w, w3, acc[r]))));
        }
    }
    #pragma unroll
    for (int r = 0; r < 32; r++) out[(ro + r)*128 + j] = acc[r];
}

// ---------------- K3: S[b,c,n,i] = base[b,c,n] . tvec[b,c,i] -----------------
__global__ void k_sdot()
{
    int bc = blockIdx.x;                // 108 blocks
    int r0 = bc * 32;
    __shared__ float Bs[32][129];
    __shared__ float Ts[32][129];
    int tid = threadIdx.x;              // 256
    for (int idx = tid; idx < 32*128; idx += 256){
        int rr = idx >> 7, dd = idx & 127;
        Bs[rr][dd] = g_base[r0*DD + idx];
        Ts[rr][dd] = g_tvec[r0*DD + idx];
    }
    __syncthreads();
    for (int p = tid; p < 1024; p += 256){
        int n = p >> 5, i = p & 31;
        float s = 0.0f;
        #pragma unroll 8
        for (int k = 0; k < 128; k++) s = fmaf(Bs[n][k], Ts[i][k], s);
        g_S[bc*1024 + p] = s;
    }
}

// ---------------- K4: uk/uv = g1@W, ck/cv = b1@W + bias -----------------------
__global__ void k_uc(const float* __restrict__ Wk, const float* __restrict__ Wv,
                     const float* __restrict__ g1, const float* __restrict__ b1,
                     const float* __restrict__ bk, const float* __restrict__ bv)
{
    int d = threadIdx.x;                // 128
    float uk=0.f, uv=0.f, ck=0.f, cv=0.f;
    for (int k = 0; k < 128; k++){
        float wk = Wk[k*128 + d], wv = Wv[k*128 + d];
        float g = g1[k], bb = b1[k];
        uk = fmaf(g, wk, uk); uv = fmaf(g, wv, uv);
        ck = fmaf(bb, wk, ck); cv = fmaf(bb, wv, cv);
    }
    g_uk[d] = uk; g_uv[d] = uv;
    g_ck[d] = ck + bk[d]; g_cv[d] = cv + bv[d];
}

// ---------------- K5: per-step query rows + residual rows --------------------
__global__ void k_q(const float* __restrict__ Wq, const float* __restrict__ bq,
                    const float* __restrict__ g1, const float* __restrict__ b1)
{
    int bi = blockIdx.x;                // 128 = b*32 + i
    int b = bi >> 5, i = bi & 31;
    int d = threadIdx.x;                // 128
    int r = b*LL + i;                   // row (b, c=0, n=i)

    __shared__ float hs[128];
    float mu  = g_mb[r] - g_mt[r];
    float S   = g_S[(b*NCC)*1024 + i*32 + i];
    float var = (g_ssb[r] - 2.0f*S + g_sst[r]) * (1.0f/128.0f) - mu*mu;
    float rstd = rsqrtf(var + 1e-5f);

    float a = g_base[r*DD + d] - g_tvec[r*DD + d];
    g_arow[bi*DD + d] = a;
    hs[d] = (a - mu)*rstd*g1[d] + b1[d];
    __syncthreads();

    float q = bq[d];
    for (int k = 0; k < 128; k++) q = fmaf(hs[k], Wq[k*128 + d], q);
    g_Q[bi*DD + d] = q;
}

// ---------------- K6: single-query attention per (b,i) -----------------------
__global__ void k_attn(const float* __restrict__ Wo, const float* __restrict__ bo,
                       const int* __restrict__ mask)
{
    int bi = blockIdx.x;                // 128
    int b = bi >> 5, i = bi & 31;
    int tid = threadIdx.x;              // 256

    __shared__ float qs[128], uks[128], cks[128], uvs[128], cvs[128];
    __shared__ float mus[LL], rstds[LL];
    __shared__ float sc[HH*LL];         // [h][l]
    __shared__ float atts[128];
    __shared__ int   mk[32];

    if (tid < 128){
        qs[tid]  = g_Q[bi*DD + tid];
        uks[tid] = g_uk[tid]; cks[tid] = g_ck[tid];
        uvs[tid] = g_uv[tid]; cvs[tid] = g_cv[tid];
    }
    if (tid < 32) mk[tid] = mask[b*NN + tid];

    // LN stats for all 864 keys of this step
    for (int l = tid; l < LL; l += 256){
        int c = l >> 5, n = l & 31;
        int rt = b*LL + c*32 + i;       // tvec row (b,c,i)
        int rb = b*LL + l;              // base row
        float mu  = g_mb[rb] - g_mt[rt];
        float S   = g_S[(b*NCC + c)*1024 + n*32 + i];
        float var = (g_ssb[rb] - 2.0f*S + g_sst[rt]) * (1.0f/128.0f) - mu*mu;
        mus[l]   = mu;
        rstds[l] = rsqrtf(var + 1e-5f);
    }
    __syncthreads();

    // scores: reconstruct K on the fly, per (l,h)
    for (int idx = tid; idx < LL*HH; idx += 256){
        int l = idx >> 3, h = idx & 7;
        int c = l >> 5, n = l & 31;
        float mu = mus[l], rstd = rstds[l];
        const float4* Pk4 = (const float4*)&g_Pk[(b*LL + l)*DD + h*16];
        const float4* Tk4 = (const float4*)&g_Tk[(b*LL + c*32 + i)*DD + h*16];
        float s = 0.0f;
        #pragma unroll
        for (int j4 = 0; j4 < 4; j4++){
            float4 p = Pk4[j4], t = Tk4[j4];
            int jb = h*16 + j4*4;
            float k0 = rstd*(p.x - t.x - mu*uks[jb+0]) + cks[jb+0];
            float k1 = rstd*(p.y - t.y - mu*uks[jb+1]) + cks[jb+1];
            float k2 = rstd*(p.z - t.z - mu*uks[jb+2]) + cks[jb+2];
            float k3 = rstd*(p.w - t.w - mu*uks[jb+3]) + cks[jb+3];
            s = fmaf(qs[jb+0], k0, fmaf(qs[jb+1], k1,
                fmaf(qs[jb+2], k2, fmaf(qs[jb+3], k3, s))));
        }
        s *= 0.25f;                      // 1/sqrt(16)
        if (mk[n] == 0) s = -1e9f;
        sc[h*LL + l] = s;
    }
    __syncthreads();

    // softmax: one warp per head
    {
        int w = tid >> 5, lane = tid & 31;
        float m = -3.4e38f;
        for (int l = lane; l < LL; l += 32) m = fmaxf(m, sc[w*LL + l]);
        #pragma unroll
        for (int o = 16; o; o >>= 1) m = fmaxf(m, __shfl_xor_sync(0xffffffffu, m, o));
        float sum = 0.0f;
        for (int l = lane; l < LL; l += 32){
            float e = expf(sc[w*LL + l] - m);
            sc[w*LL + l] = e;
            sum += e;
        }
        #pragma unroll
        for (int o = 16; o; o >>= 1) sum += __shfl_xor_sync(0xffffffffu, sum, o);
        float inv = 1.0f / sum;
        for (int l = lane; l < LL; l += 32) sc[w*LL + l] *= inv;
    }
    __syncthreads();

    // weighted V, reconstructing V on the fly (thread = output dim d)
    if (tid < 128){
        int d = tid, h = d >> 4;
        float uv = uvs[d], cv = cvs[d];
        float acc = 0.0f;
        for (int c = 0; c < NCC; c++){
            float tv = g_Tv[(b*LL + c*32 + i)*DD + d];
            int lb = c*32;
            #pragma unroll 8
            for (int n = 0; n < 32; n++){
                int l = lb + n;
                float v = rstds[l]*(g_Pv[(b*LL + l)*DD + d] - tv - mus[l]*uv) + cv;
                acc = fmaf(sc[h*LL + l], v, acc);
            }
        }
        atts[d] = acc;
    }
    __syncthreads();

    // output projection + residual
    if (tid < 128){
        int dp = tid;
        float o = bo[dp];
        for (int k = 0; k < 128; k++) o = fmaf(atts[k], Wo[k*128 + dp], o);
        g_y[bi*DD + dp] = g_arow[bi*DD + dp] + o;
    }
}

// ---------------- K7: final LN + FFN + residual ------------------------------
__global__ void k_ffn(const float* __restrict__ g2, const float* __restrict__ b2,
                      const float* __restrict__ W1, const float* __restrict__ bf1,
                      const float* __restrict__ W2, const float* __restrict__ bf2,
                      float* __restrict__ out)
{
    int row = blockIdx.x;               // 128 = b*32 + n
    int tid = threadIdx.x;              // 256
    __shared__ float ys[128], hs[128], zs[512];
    __shared__ float rsm[4][2];
    __shared__ float stat[2];

    if (tid < 128) ys[tid] = g_y[row*DD + tid];
    __syncthreads();

    if (tid < 128){
        float v = ys[tid];
        float s = warpSum(v), s2 = warpSum(v*v);
        if ((tid & 31) == 0){ rsm[tid>>5][0] = s; rsm[tid>>5][1] = s2; }
    }
    __syncthreads();
    if (tid == 0){
        float s  = rsm[0][0]+rsm[1][0]+rsm[2][0]+rsm[3][0];
        float s2 = rsm[0][1]+rsm[1][1]+rsm[2][1]+rsm[3][1];
        float m = s * (1.0f/128.0f);
        stat[0] = m;
        stat[1] = rsqrtf(s2*(1.0f/128.0f) - m*m + 1e-5f);
    }
    __syncthreads();
    float mu = stat[0], rstd = stat[1];
    if (tid < 128) hs[tid] = (ys[tid] - mu)*rstd*g2[tid] + b2[tid];
    __syncthreads();

    for (int j = tid; j < DFF; j += 256){
        float z = bf1[j];
        for (int k = 0; k < 128; k++) z = fmaf(hs[k], W1[k*DFF + j], z);
        zs[j] = fmaxf(z, 0.0f);
    }
    __syncthreads();

    if (tid < 128){
        int dp = tid;
        float o = bf2[dp];
        #pragma unroll 4
        for (int j = 0; j < DFF; j++) o = fmaf(zs[j], W2[j*128 + dp], o);
        out[row*DD + dp] = ys[dp] + o;
    }
}

// ---------------- launch ------------------------------------------------------
extern "C" void kernel_launch(void* const* d_in, const int* in_sizes, int n_in,
                              void* d_out, int out_size)
{
    const float* x      = (const float*)d_in[0];
    const int*   mask   = (const int*)  d_in[1];
    const float* coords = (const float*)d_in[2];
    const float* Wp = (const float*)d_in[3],  *bp  = (const float*)d_in[4];
    const float* Wq = (const float*)d_in[5],  *bq  = (const float*)d_in[6];
    const float* Wk = (const float*)d_in[7],  *bk  = (const float*)d_in[8];
    const float* Wv = (const float*)d_in[9],  *bv  = (const float*)d_in[10];
    const float* Wo = (const float*)d_in[11], *bo  = (const float*)d_in[12];
    const float* g1 = (const float*)d_in[13], *b1  = (const float*)d_in[14];
    const float* g2 = (const float*)d_in[15], *b2  = (const float*)d_in[16];
    const float* W1 = (const float*)d_in[17], *bf1 = (const float*)d_in[18];
    const float* W2 = (const float*)d_in[19], *bf2 = (const float*)d_in[20];
    float* out = (float*)d_out;

    k_prep   <<<ROWS, 128>>>(x, coords, Wp, bp);
    k_gemm_pt<<<2*ROWS/32, 256>>>(Wk, Wv, g1);
    k_sdot   <<<BB*NCC, 256>>>();
    k_uc     <<<1, 128>>>(Wk, Wv, g1, b1, bk, bv);
    k_q      <<<BB*NN, 128>>>(Wq, bq, g1, b1);
    k_attn   <<<BB*NN, 256>>>(Wo, bo, mask);
    k_ffn    <<<BB*NN, 256>>>(g2, b2, W1, bf1, W2, bf2, out);
}

// round 2
// speedup vs baseline: 1.6126x; 1.6126x over previous
#include <cuda_runtime.h>
#include <math.h>

#define BB 4
#define NN 32
#define DD 128
#define HH 8
#define NCC 27
#define DFF 512
#define LL (NCC*NN)        // 864
#define ROWS (BB*LL)       // 3456

// ---------------- scratch (static device globals; no allocation) -------------
__device__ __align__(16) float g_base[ROWS*DD];
__device__ __align__(16) float g_tvec[ROWS*DD];
__device__ __align__(16) float g_Pk[ROWS*DD];
__device__ __align__(16) float g_Pv[ROWS*DD];
__device__ __align__(16) float g_Tk[ROWS*DD];
__device__ __align__(16) float g_Tv[ROWS*DD];
__device__ float g_mb[ROWS], g_ssb[ROWS];
__device__ float g_mt[ROWS], g_sst[ROWS];
__device__ float g_S[BB*NCC*NN*NN];
__device__ __align__(16) float g_y[BB*NN*DD];
__device__ float g_uk[DD], g_uv[DD], g_ck[DD], g_cv[DD];

__inline__ __device__ float warpSum(float v){
    #pragma unroll
    for (int o = 16; o; o >>= 1) v += __shfl_down_sync(0xffffffffu, v, o);
    return v;
}

// ---------------- K1: base/tvec + per-row stats, plus uc blocks --------------
__global__ void k_prep(const float* __restrict__ x, const float* __restrict__ coords,
                       const float* __restrict__ Wp, const float* __restrict__ bp,
                       const float* __restrict__ Wk, const float* __restrict__ Wv,
                       const float* __restrict__ g1, const float* __restrict__ b1,
                       const float* __restrict__ bk, const float* __restrict__ bv)
{
    __shared__ float sm[4][4];
    int bid = blockIdx.x;
    if (bid < ROWS){
        int r = bid;
        int n = r & 31;
        int b = r / (NCC*NN);
        int d = threadIdx.x;

        float c0 = coords[r*3+0], c1 = coords[r*3+1], c2 = coords[r*3+2];
        float t  = c0*Wp[d] + c1*Wp[DD+d] + c2*Wp[2*DD+d];
        float bs = x[(b*NN+n)*DD + d] + t + bp[d];
        g_tvec[r*DD + d] = t;
        g_base[r*DD + d] = bs;

        float s0 = warpSum(t), s1 = warpSum(t*t), s2 = warpSum(bs), s3 = warpSum(bs*bs);
        int lane = d & 31, w = d >> 5;
        if (lane == 0){ sm[w][0]=s0; sm[w][1]=s1; sm[w][2]=s2; sm[w][3]=s3; }
        __syncthreads();
        if (d < 4){
            float a = sm[0][d] + sm[1][d] + sm[2][d] + sm[3][d];
            if (d == 0) g_mt[r]  = a * (1.0f/128.0f);
            if (d == 1) g_sst[r] = a;
            if (d == 2) g_mb[r]  = a * (1.0f/128.0f);
            if (d == 3) g_ssb[r] = a;
        }
    } else {
        // uc: one block per output dim d, 128 threads reduce over k
        int d = bid - ROWS;
        int k = threadIdx.x;
        float g = g1[k], bb = b1[k];
        float wk = Wk[k*128 + d], wv = Wv[k*128 + d];
        float v0 = g*wk, v1 = g*wv, v2 = bb*wk, v3 = bb*wv;
        float s0 = warpSum(v0), s1 = warpSum(v1), s2 = warpSum(v2), s3 = warpSum(v3);
        int lane = k & 31, w = k >> 5;
        if (lane == 0){ sm[w][0]=s0; sm[w][1]=s1; sm[w][2]=s2; sm[w][3]=s3; }
        __syncthreads();
        if (k < 4){
            float a = sm[0][k] + sm[1][k] + sm[2][k] + sm[3][k];
            if (k == 0) g_uk[d] = a;
            if (k == 1) g_uv[d] = a;
            if (k == 2) g_ck[d] = a + bk[d];
            if (k == 3) g_cv[d] = a + bv[d];
        }
    }
}

// ---------------- K2: hoisted GEMMs + S dot-products (fused grid) ------------
__global__ void k_gemm_sdot(const float* __restrict__ Wk, const float* __restrict__ Wv,
                            const float* __restrict__ g1)
{
    __shared__ __align__(16) float sbuf[2*32*129];   // 33 KB, reused by both halves
    int bid = blockIdx.x;
    int tid = threadIdx.x;              // 256

    if (bid < 216){
        // -------- GEMM tile: 32 rows x 128 cols, two weight matrices --------
        float (*As)[128] = (float(*)[128])sbuf;
        int m0 = bid * 32;
        const float* src; float* outK; float* outV; int ro;
        if (m0 < ROWS){ src = g_base + m0*DD;        outK = g_Pk; outV = g_Pv; ro = m0; }
        else          { src = g_tvec + (m0-ROWS)*DD; outK = g_Tk; outV = g_Tv; ro = m0-ROWS; }

        for (int idx = tid; idx < 32*128; idx += 256){
            int dd = idx & 127;
            As[idx >> 7][dd] = src[idx] * g1[dd];
        }
        __syncthreads();

        int j = tid & 127;
        const float* W = (tid < 128) ? Wk : Wv;
        float*     out = (tid < 128) ? outK : outV;

        float acc[32];
        #pragma unroll
        for (int r = 0; r < 32; r++) acc[r] = 0.0f;

        for (int k4 = 0; k4 < 32; k4++){
            float w0 = W[(4*k4+0)*128 + j];
            float w1 = W[(4*k4+1)*128 + j];
            float w2 = W[(4*k4+2)*128 + j];
            float w3 = W[(4*k4+3)*128 + j];
            #pragma unroll
            for (int r = 0; r < 32; r++){
                float4 a = *(const float4*)&As[r][4*k4];
                acc[r] = fmaf(a.x, w0, fmaf(a.y, w1, fmaf(a.z, w2, fmaf(a.w, w3, acc[r]))));
            }
        }
        #pragma unroll
        for (int r = 0; r < 32; r++) out[(ro + r)*128 + j] = acc[r];
    } else {
        // -------- S[b,c,n,i] = base[b,c,n] . tvec[b,c,i] --------
        float (*Bs)[129] = (float(*)[129])sbuf;
        float (*Ts)[129] = (float(*)[129])(sbuf + 32*129);
        int bc = bid - 216;             // 108 blocks
        int r0 = bc * 32;
        for (int idx = tid; idx < 32*128; idx += 256){
            int rr = idx >> 7, dd = idx & 127;
            Bs[rr][dd] = g_base[r0*DD + idx];
            Ts[rr][dd] = g_tvec[r0*DD + idx];
        }
        __syncthreads();
        for (int p = tid; p < 1024; p += 256){
            int n = p >> 5, i = p & 31;
            float s = 0.0f;
            #pragma unroll 8
            for (int k = 0; k < 128; k++) s = fmaf(Bs[n][k], Ts[i][k], s);
            g_S[bc*1024 + p] = s;
        }
    }
}

// ---------------- K3: attention per (b,i), q fused, 512 threads ---------------
__global__ void __launch_bounds__(512)
k_attn(const float* __restrict__ Wq, const float* __restrict__ bq,
       const float* __restrict__ Wo, const float* __restrict__ bo,
       const float* __restrict__ g1, const float* __restrict__ b1,
       const int* __restrict__ mask)
{
    int bi = blockIdx.x;                // 128
    int b = bi >> 5, i = bi & 31;
    int tid = threadIdx.x;              // 512

    __shared__ float qs[128], uks[128], cks[128], uvs[128], cvs[128];
    __shared__ float mus[LL], rstds[LL];
    __shared__ float sc[HH*LL];
    __shared__ float attp[4][128];
    __shared__ float atts[128];
    __shared__ float op[4][128];
    __shared__ float as_[128], hs[128];
    __shared__ int   mk[32];

    if (tid < 128){
        uks[tid] = g_uk[tid]; cks[tid] = g_ck[tid];
        uvs[tid] = g_uv[tid]; cvs[tid] = g_cv[tid];
    }
    if (tid >= 480) mk[tid-480] = mask[b*NN + (tid-480)];

    // LN stats for all 864 keys of this step
    for (int l = tid; l < LL; l += 512){
        int c = l >> 5, n = l & 31;
        int rt = b*LL + c*32 + i;
        int rb = b*LL + l;
        float mu  = g_mb[rb] - g_mt[rt];
        float S   = g_S[(b*NCC + c)*1024 + n*32 + i];
        float var = (g_ssb[rb] - 2.0f*S + g_sst[rt]) * (1.0f/128.0f) - mu*mu;
        mus[l]   = mu;
        rstds[l] = rsqrtf(var + 1e-5f);
    }
    __syncthreads();

    // query row: a, hn (row l = i corresponds to c=0,n=i)
    if (tid < 128){
        int r = b*LL + i;
        float a = g_base[r*DD + tid] - g_tvec[r*DD + tid];
        as_[tid] = a;
        hs[tid] = (a - mus[i])*rstds[i]*g1[tid] + b1[tid];
    }
    __syncthreads();

    // q projection, 4-way split over k
    {
        int dp = tid & 127, part = tid >> 7;
        float q = 0.0f;
        int k0 = part*32;
        #pragma unroll
        for (int k = 0; k < 32; k++) q = fmaf(hs[k0+k], Wq[(k0+k)*128 + dp], q);
        op[part][dp] = q;
        __syncthreads();
        if (tid < 128) qs[tid] = op[0][tid]+op[1][tid]+op[2][tid]+op[3][tid] + bq[tid];
    }
    __syncthreads();

    // scores: reconstruct K on the fly, per (l,h)
    for (int idx = tid; idx < LL*HH; idx += 512){
        int l = idx >> 3, h = idx & 7;
        int c = l >> 5, n = l & 31;
        float mu = mus[l], rstd = rstds[l];
        const float4* Pk4 = (const float4*)&g_Pk[(b*LL + l)*DD + h*16];
        const float4* Tk4 = (const float4*)&g_Tk[(b*LL + c*32 + i)*DD + h*16];
        float s = 0.0f;
        #pragma unroll
        for (int j4 = 0; j4 < 4; j4++){
            float4 p = Pk4[j4], t = Tk4[j4];
            int jb = h*16 + j4*4;
            float k0 = rstd*(p.x - t.x - mu*uks[jb+0]) + cks[jb+0];
            float k1 = rstd*(p.y - t.y - mu*uks[jb+1]) + cks[jb+1];
            float k2 = rstd*(p.z - t.z - mu*uks[jb+2]) + cks[jb+2];
            float k3 = rstd*(p.w - t.w - mu*uks[jb+3]) + cks[jb+3];
            s = fmaf(qs[jb+0], k0, fmaf(qs[jb+1], k1,
                fmaf(qs[jb+2], k2, fmaf(qs[jb+3], k3, s))));
        }
        s *= 0.25f;
        if (mk[n] == 0) s = -1e9f;
        sc[h*LL + l] = s;
    }
    __syncthreads();

    // softmax: one warp per head (warps 0-7)
    if (tid < 256){
        int w = tid >> 5, lane = tid & 31;
        float m = -3.4e38f;
        for (int l = lane; l < LL; l += 32) m = fmaxf(m, sc[w*LL + l]);
        #pragma unroll
        for (int o = 16; o; o >>= 1) m = fmaxf(m, __shfl_xor_sync(0xffffffffu, m, o));
        float sum = 0.0f;
        for (int l = lane; l < LL; l += 32){
            float e = __expf(sc[w*LL + l] - m);
            sc[w*LL + l] = e;
            sum += e;
        }
        #pragma unroll
        for (int o = 16; o; o >>= 1) sum += __shfl_xor_sync(0xffffffffu, sum, o);
        float inv = 1.0f / sum;
        for (int l = lane; l < LL; l += 32) sc[w*LL + l] *= inv;
    }
    __syncthreads();

    // weighted V, reconstructing V on the fly; 4-way split over c-chunks
    {
        int d = tid & 127, part = tid >> 7;
        int h = d >> 4;
        float uv = uvs[d], cv = cvs[d];
        float acc = 0.0f;
        int c0p = part*7, c1p = (part == 3) ? 27 : c0p + 7;
        for (int c = c0p; c < c1p; c++){
            float tv = g_Tv[(b*LL + c*32 + i)*DD + d];
            int lb = c*32;
            #pragma unroll 8
            for (int n = 0; n < 32; n++){
                int l = lb + n;
                float v = rstds[l]*(g_Pv[(b*LL + l)*DD + d] - tv - mus[l]*uv) + cv;
                acc = fmaf(sc[h*LL + l], v, acc);
            }
        }
        attp[part][d] = acc;
    }
    __syncthreads();
    if (tid < 128) atts[tid] = attp[0][tid]+attp[1][tid]+attp[2][tid]+attp[3][tid];
    __syncthreads();

    // output projection + residual, 4-way split over k
    {
        int dp = tid & 127, part = tid >> 7;
        float o = 0.0f;
        int k0 = part*32;
        #pragma unroll
        for (int k = 0; k < 32; k++) o = fmaf(atts[k0+k], Wo[(k0+k)*128 + dp], o);
        op[part][dp] = o;
        __syncthreads();
        if (tid < 128)
            g_y[bi*DD + tid] = as_[tid] + op[0][tid]+op[1][tid]+op[2][tid]+op[3][tid] + bo[tid];
    }
}

// ---------------- K4: final LN + FFN + residual ------------------------------
__global__ void k_ffn(const float* __restrict__ g2, const float* __restrict__ b2,
                      const float* __restrict__ W1, const float* __restrict__ bf1,
                      const float* __restrict__ W2, const float* __restrict__ bf2,
                      float* __restrict__ out)
{
    int row = blockIdx.x;               // 128 = b*32 + n
    int tid = threadIdx.x;              // 256
    __shared__ float ys[128], hs[128], zs[512];
    __shared__ float op[2][128];
    __shared__ float rsm[4][2];
    __shared__ float stat[2];

    if (tid < 128) ys[tid] = g_y[row*DD + tid];
    __syncthreads();

    if (tid < 128){
        float v = ys[tid];
        float s = warpSum(v), s2 = warpSum(v*v);
        if ((tid & 31) == 0){ rsm[tid>>5][0] = s; rsm[tid>>5][1] = s2; }
    }
    __syncthreads();
    if (tid == 0){
        float s  = rsm[0][0]+rsm[1][0]+rsm[2][0]+rsm[3][0];
        float s2 = rsm[0][1]+rsm[1][1]+rsm[2][1]+rsm[3][1];
        float m = s * (1.0f/128.0f);
        stat[0] = m;
        stat[1] = rsqrtf(s2*(1.0f/128.0f) - m*m + 1e-5f);
    }
    __syncthreads();
    float mu = stat[0], rstd = stat[1];
    if (tid < 128) hs[tid] = (ys[tid] - mu)*rstd*g2[tid] + b2[tid];
    __syncthreads();

    // first GEMM: 512 outputs, 2 per thread
    for (int j = tid; j < DFF; j += 256){
        float z = bf1[j];
        #pragma unroll 4
        for (int k = 0; k < 128; k++) z = fmaf(hs[k], W1[k*DFF + j], z);
        zs[j] = fmaxf(z, 0.0f);
    }
    __syncthreads();

    // second GEMM: 2-way split over j
    {
        int dp = tid & 127, part = tid >> 7;
        float o = 0.0f;
        int j0 = part*256;
        #pragma unroll 4
        for (int j = 0; j < 256; j++) o = fmaf(zs[j0+j], W2[(j0+j)*128 + dp], o);
        op[part][dp] = o;
        __syncthreads();
        if (tid < 128)
            out[row*DD + tid] = ys[tid] + op[0][tid] + op[1][tid] + bf2[tid];
    }
}

// ---------------- launch ------------------------------------------------------
extern "C" void kernel_launch(void* const* d_in, const int* in_sizes, int n_in,
                              void* d_out, int out_size)
{
    const float* x      = (const float*)d_in[0];
    const int*   mask   = (const int*)  d_in[1];
    const float* coords = (const float*)d_in[2];
    const float* Wp = (const float*)d_in[3],  *bp  = (const float*)d_in[4];
    const float* Wq = (const float*)d_in[5],  *bq  = (const float*)d_in[6];
    const float* Wk = (const float*)d_in[7],  *bk  = (const float*)d_in[8];
    const float* Wv = (const float*)d_in[9],  *bv  = (const float*)d_in[10];
    const float* Wo = (const float*)d_in[11], *bo  = (const float*)d_in[12];
    const float* g1 = (const float*)d_in[13], *b1  = (const float*)d_in[14];
    const float* g2 = (const float*)d_in[15], *b2  = (const float*)d_in[16];
    const float* W1 = (const float*)d_in[17], *bf1 = (const float*)d_in[18];
    const float* W2 = (const float*)d_in[19], *bf2 = (const float*)d_in[20];
    float* out = (float*)d_out;

    k_prep     <<<ROWS + DD, 128>>>(x, coords, Wp, bp, Wk, Wv, g1, b1, bk, bv);
    k_gemm_sdot<<<216 + 108, 256>>>(Wk, Wv, g1);
    k_attn     <<<BB*NN, 512>>>(Wq, bq, Wo, bo, g1, b1, mask);
    k_ffn      <<<BB*NN, 256>>>(g2, b2, W1, bf1, W2, bf2, out);
}